// round 6
// baseline (speedup 1.0000x reference)
#include <cuda_runtime.h>
#include <math.h>

// TtMambaSSM (B=256, D=5120, R=160, N=16)
//   zero  : clear TBC accumulator
//   gemm1 : TBC = x @ [W_dt_low|W_B|W_C]   (256x192xK5120, 8x8 micro, split-K=40 + atomics)
//   gemm2 : delta = softplus(T @ W_dt + b) (256x5120xK160, 8x8 micro)
//   elem  : out = x*(D + delta*BC) + sum_n exp(delta*A)*h0*Cp  (1280 blocks, coalesced)

typedef unsigned long long ull;

#define Bsz 256
#define Dsz 5120
#define NC  192

__device__ float g_TBC[Bsz * NC];
__device__ float g_delta[Bsz * Dsz];

__device__ __forceinline__ ull pack2(float lo, float hi) {
    ull r; asm("mov.b64 %0, {%1, %2};" : "=l"(r) : "f"(lo), "f"(hi)); return r;
}
__device__ __forceinline__ void ffma2(ull& d, ull a, ull b) {
    asm("fma.rn.f32x2 %0, %1, %2, %0;" : "+l"(d) : "l"(a), "l"(b));
}
__device__ __forceinline__ float2 unpack2(ull v) {
    float2 f; asm("mov.b64 {%0, %1}, %2;" : "=f"(f.x), "=f"(f.y) : "l"(v)); return f;
}

__global__ void zero_kernel() {
    int q = blockIdx.x * 256 + threadIdx.x;
    if (q < Bsz * NC / 4) *(float4*)(g_TBC + q * 4) = make_float4(0.f, 0.f, 0.f, 0.f);
}

// virtual concatenated weight read: col j of [W_dt_low | W_B | W_C] (192 cols)
__device__ __forceinline__ float4 loadW(const float* __restrict__ Wlow,
                                        const float* __restrict__ WB,
                                        const float* __restrict__ WC,
                                        int k, int j) {
    if (j < 160) return *(const float4*)(Wlow + k * 160 + j);
    if (j < 176) return *(const float4*)(WB + k * 16 + (j - 160));
    return *(const float4*)(WC + k * 16 + (j - 176));
}

// ---------------- GEMM1: 256x192 += x(256x5120) @ Wcat ----------------
// tiles 128m x 64n, BK=16, k-chunk 128, grid (6, 40), 128 threads, 8x8 micro
__global__ void __launch_bounds__(128) gemm1_kernel(const float* __restrict__ x,
                                                    const float* __restrict__ Wlow,
                                                    const float* __restrict__ WB,
                                                    const float* __restrict__ WC)
{
    __shared__ float As[2][16][132];   // [k][m]
    __shared__ float Bs[2][16][68];    // [k][n]

    const int m0 = (blockIdx.x & 1) * 128;
    const int n0 = (blockIdx.x >> 1) * 64;
    const int k0 = blockIdx.y * 128;
    const int tid = threadIdx.x;
    const int ty = tid >> 3;            // 0..15  (m micro)
    const int tx = tid & 7;             // 0..7   (n micro)
    const int lr  = tid >> 2;           // 0..31  a rows
    const int lkq = (tid & 3) * 4;      // a k-quad
    const int bkr = tid >> 4;           // 0..7   b k rows
    const int bnq = (tid & 15) * 4;     // b n offset

    ull acc[4][8];
    const ull z0 = pack2(0.f, 0.f);
#pragma unroll
    for (int i = 0; i < 4; i++)
#pragma unroll
        for (int j = 0; j < 8; j++) acc[i][j] = z0;

    float4 av[4], bv[2];
#pragma unroll
    for (int j = 0; j < 4; j++)
        av[j] = *(const float4*)(x + (m0 + lr + 32 * j) * Dsz + k0 + lkq);
    bv[0] = loadW(Wlow, WB, WC, k0 + bkr,     n0 + bnq);
    bv[1] = loadW(Wlow, WB, WC, k0 + bkr + 8, n0 + bnq);

#pragma unroll
    for (int j = 0; j < 4; j++) {
        As[0][lkq + 0][lr + 32 * j] = av[j].x;
        As[0][lkq + 1][lr + 32 * j] = av[j].y;
        As[0][lkq + 2][lr + 32 * j] = av[j].z;
        As[0][lkq + 3][lr + 32 * j] = av[j].w;
    }
    *(float4*)&Bs[0][bkr][bnq]     = bv[0];
    *(float4*)&Bs[0][bkr + 8][bnq] = bv[1];
    __syncthreads();

    for (int it = 0; it < 8; it++) {
        const int cur = it & 1;
        if (it < 7) {
            const int kb = k0 + (it + 1) * 16;
#pragma unroll
            for (int j = 0; j < 4; j++)
                av[j] = *(const float4*)(x + (m0 + lr + 32 * j) * Dsz + kb + lkq);
            bv[0] = loadW(Wlow, WB, WC, kb + bkr,     n0 + bnq);
            bv[1] = loadW(Wlow, WB, WC, kb + bkr + 8, n0 + bnq);
        }
#pragma unroll
        for (int kk = 0; kk < 16; kk++) {
            float4 a0 = *(const float4*)&As[cur][kk][ty * 8];
            float4 a1 = *(const float4*)&As[cur][kk][ty * 8 + 4];
            float4 b0 = *(const float4*)&Bs[cur][kk][tx * 8];
            float4 b1 = *(const float4*)&Bs[cur][kk][tx * 8 + 4];
            ull aP0 = pack2(a0.x, a0.y), aP1 = pack2(a0.z, a0.w);
            ull aP2 = pack2(a1.x, a1.y), aP3 = pack2(a1.z, a1.w);
            ull bd;
#define G1STEP(jj, bb) \
            bd = pack2(bb, bb); \
            ffma2(acc[0][jj], aP0, bd); ffma2(acc[1][jj], aP1, bd); \
            ffma2(acc[2][jj], aP2, bd); ffma2(acc[3][jj], aP3, bd);
            G1STEP(0, b0.x) G1STEP(1, b0.y) G1STEP(2, b0.z) G1STEP(3, b0.w)
            G1STEP(4, b1.x) G1STEP(5, b1.y) G1STEP(6, b1.z) G1STEP(7, b1.w)
#undef G1STEP
        }
        if (it < 7) {
            const int nxt = cur ^ 1;
#pragma unroll
            for (int j = 0; j < 4; j++) {
                As[nxt][lkq + 0][lr + 32 * j] = av[j].x;
                As[nxt][lkq + 1][lr + 32 * j] = av[j].y;
                As[nxt][lkq + 2][lr + 32 * j] = av[j].z;
                As[nxt][lkq + 3][lr + 32 * j] = av[j].w;
            }
            *(float4*)&Bs[nxt][bkr][bnq]     = bv[0];
            *(float4*)&Bs[nxt][bkr + 8][bnq] = bv[1];
        }
        __syncthreads();
    }

#pragma unroll
    for (int i = 0; i < 4; i++)
#pragma unroll
        for (int j = 0; j < 8; j++) {
            float2 v = unpack2(acc[i][j]);
            const int row = m0 + ty * 8 + 2 * i;
            const int col = n0 + tx * 8 + j;
            atomicAdd(&g_TBC[row * NC + col], v.x);
            atomicAdd(&g_TBC[(row + 1) * NC + col], v.y);
        }
}

// ---------------- GEMM2: delta = softplus(TBC[:, :160] @ W_dt + b) ----------------
// tiles 64m x 128n, BK=16, K=160 (10 iters), grid (40, 4), 128 threads, 8x8 micro
__global__ void __launch_bounds__(128) gemm2_kernel(const float* __restrict__ Wdt,
                                                    const float* __restrict__ bias)
{
    __shared__ float As[2][16][68];    // [k][m]
    __shared__ float Bs[2][16][132];   // [k][n]
    __shared__ float bias_s[128];

    const int n0 = blockIdx.x * 128;
    const int m0 = blockIdx.y * 64;
    const int tid = threadIdx.x;
    const int ty = tid >> 4;            // 0..7   (m micro)
    const int tx = tid & 15;            // 0..15  (n micro)
    const int lr  = tid >> 2;           // 0..31  a rows
    const int lkq = (tid & 3) * 4;
    const int bkr = tid >> 5;           // 0..3   b k rows (+4 step)
    const int bnq = (tid & 31) * 4;     // b n offset

    bias_s[tid] = bias[n0 + tid];

    ull acc[4][8];
    const ull z0 = pack2(0.f, 0.f);
#pragma unroll
    for (int i = 0; i < 4; i++)
#pragma unroll
        for (int j = 0; j < 8; j++) acc[i][j] = z0;

    float4 av[2], bv[4];
#pragma unroll
    for (int j = 0; j < 2; j++)
        av[j] = *(const float4*)(g_TBC + (m0 + lr + 32 * j) * NC + lkq);
#pragma unroll
    for (int i = 0; i < 4; i++)
        bv[i] = *(const float4*)(Wdt + (bkr + 4 * i) * Dsz + n0 + bnq);

#pragma unroll
    for (int j = 0; j < 2; j++) {
        As[0][lkq + 0][lr + 32 * j] = av[j].x;
        As[0][lkq + 1][lr + 32 * j] = av[j].y;
        As[0][lkq + 2][lr + 32 * j] = av[j].z;
        As[0][lkq + 3][lr + 32 * j] = av[j].w;
    }
#pragma unroll
    for (int i = 0; i < 4; i++)
        *(float4*)&Bs[0][bkr + 4 * i][bnq] = bv[i];
    __syncthreads();

    for (int it = 0; it < 10; it++) {
        const int cur = it & 1;
        if (it < 9) {
            const int kb = (it + 1) * 16;
#pragma unroll
            for (int j = 0; j < 2; j++)
                av[j] = *(const float4*)(g_TBC + (m0 + lr + 32 * j) * NC + kb + lkq);
#pragma unroll
            for (int i = 0; i < 4; i++)
                bv[i] = *(const float4*)(Wdt + (kb + bkr + 4 * i) * Dsz + n0 + bnq);
        }
#pragma unroll
        for (int kk = 0; kk < 16; kk++) {
            float4 a0 = *(const float4*)&As[cur][kk][ty * 8];
            float4 a1 = *(const float4*)&As[cur][kk][ty * 8 + 4];
            float4 b0 = *(const float4*)&Bs[cur][kk][tx * 8];
            float4 b1 = *(const float4*)&Bs[cur][kk][tx * 8 + 4];
            ull aP0 = pack2(a0.x, a0.y), aP1 = pack2(a0.z, a0.w);
            ull aP2 = pack2(a1.x, a1.y), aP3 = pack2(a1.z, a1.w);
            ull bd;
#define G2STEP(jj, bb) \
            bd = pack2(bb, bb); \
            ffma2(acc[0][jj], aP0, bd); ffma2(acc[1][jj], aP1, bd); \
            ffma2(acc[2][jj], aP2, bd); ffma2(acc[3][jj], aP3, bd);
            G2STEP(0, b0.x) G2STEP(1, b0.y) G2STEP(2, b0.z) G2STEP(3, b0.w)
            G2STEP(4, b1.x) G2STEP(5, b1.y) G2STEP(6, b1.z) G2STEP(7, b1.w)
#undef G2STEP
        }
        if (it < 9) {
            const int nxt = cur ^ 1;
#pragma unroll
            for (int j = 0; j < 2; j++) {
                As[nxt][lkq + 0][lr + 32 * j] = av[j].x;
                As[nxt][lkq + 1][lr + 32 * j] = av[j].y;
                As[nxt][lkq + 2][lr + 32 * j] = av[j].z;
                As[nxt][lkq + 3][lr + 32 * j] = av[j].w;
            }
#pragma unroll
            for (int i = 0; i < 4; i++)
                *(float4*)&Bs[nxt][bkr + 4 * i][bnq] = bv[i];
        }
        __syncthreads();
    }

#pragma unroll
    for (int i = 0; i < 4; i++)
#pragma unroll
        for (int j = 0; j < 8; j++) {
            float2 v = unpack2(acc[i][j]);
            const int row = m0 + ty * 8 + 2 * i;
            const int col = n0 + tx * 8 + j;
            const float bb = bias_s[tx * 8 + j];
            float t0 = v.x + bb, t1 = v.y + bb;
            g_delta[row * Dsz + col]       = (t0 > 20.0f) ? t0 : log1pf(expf(t0));
            g_delta[(row + 1) * Dsz + col] = (t1 > 20.0f) ? t1 : log1pf(expf(t1));
        }
}

// ---------------- elem: out = x*(D + delta*BC) + sum_n exp(delta*A)*h0*Cp ----------------
// grid (20, 64): d-chunk 256, b-chunk 4. 256 threads; lane quad per d, 4 states/lane.
__global__ void __launch_bounds__(256) elem_kernel(const float* __restrict__ x,
                                                   const float* __restrict__ Ag,
                                                   const float* __restrict__ Dg,
                                                   const float* __restrict__ h0,
                                                   float* __restrict__ out)
{
    __shared__ float delta_s[4 * 256];
    __shared__ float y_s[4 * 256];
    __shared__ float D_s[256];
    __shared__ float Cp_s[4][16];
    __shared__ float BC_s[4];

    const int d0 = blockIdx.x * 256;
    const int b0 = blockIdx.y * 4;
    const int tid = threadIdx.x;

#pragma unroll
    for (int r = 0; r < 4; r++)
        delta_s[r * 256 + tid] = g_delta[(size_t)(b0 + r) * Dsz + d0 + tid];
    D_s[tid] = Dg[d0 + tid];
    if (tid < 64) {
        const int bb = tid >> 4, n = tid & 15;
        Cp_s[bb][n] = g_TBC[(b0 + bb) * NC + 176 + n];
    }
    __syncthreads();
    if (tid < 4) {
        float s = 0.0f;
#pragma unroll
        for (int n = 0; n < 16; n++)
            s += g_TBC[(b0 + tid) * NC + 160 + n] * Cp_s[tid][n];
        BC_s[tid] = s;
    }
    __syncthreads();

    const int nq = tid & 3;       // state quad 0..3
    const int dq = tid >> 2;      // local d 0..63

#pragma unroll
    for (int i = 0; i < 4; i++) {
        const int dloc = i * 64 + dq;
        const int d = d0 + dloc;
        const float4 Av = *(const float4*)(Ag + d * 16 + nq * 4);
        float4 hv[4];
#pragma unroll
        for (int b = 0; b < 4; b++)
            hv[b] = *(const float4*)(h0 + ((size_t)(b0 + b) * Dsz + d) * 16 + nq * 4);
#pragma unroll
        for (int b = 0; b < 4; b++) {
            const float delta = delta_s[b * 256 + dloc];
            const float* Cr = &Cp_s[b][nq * 4];
            float y = __expf(delta * Av.x) * (hv[b].x * Cr[0])
                    + __expf(delta * Av.y) * (hv[b].y * Cr[1])
                    + __expf(delta * Av.z) * (hv[b].z * Cr[2])
                    + __expf(delta * Av.w) * (hv[b].w * Cr[3]);
            y += __shfl_xor_sync(0xffffffffu, y, 1);
            y += __shfl_xor_sync(0xffffffffu, y, 2);
            if (nq == 0) y_s[b * 256 + dloc] = y;
        }
    }
    __syncthreads();

#pragma unroll
    for (int r = 0; r < 4; r++) {
        const int idx = r * 256 + tid;
        const size_t g = (size_t)(b0 + r) * Dsz + d0 + tid;
        out[g] = x[g] * (D_s[tid] + delta_s[idx] * BC_s[r]) + y_s[idx];
    }
}

extern "C" void kernel_launch(void* const* d_in, const int* in_sizes, int n_in,
                              void* d_out, int out_size) {
    const float* x    = (const float*)d_in[0];
    const float* Wlow = (const float*)d_in[1];
    const float* Wdt  = (const float*)d_in[2];
    const float* bdt  = (const float*)d_in[3];
    const float* WB   = (const float*)d_in[4];
    const float* WC   = (const float*)d_in[5];
    const float* A    = (const float*)d_in[6];
    const float* D    = (const float*)d_in[7];
    const float* h0   = (const float*)d_in[8];
    float* out = (float*)d_out;

    zero_kernel<<<(Bsz * NC / 4 + 255) / 256, 256>>>();
    gemm1_kernel<<<dim3(6, 40), 128>>>(x, Wlow, WB, WC);
    gemm2_kernel<<<dim3(40, 4), 128>>>(Wdt, bdt);
    elem_kernel<<<dim3(20, 64), 256>>>(x, A, D, h0, out);
}

// round 7
// speedup vs baseline: 1.1561x; 1.1561x over previous
#include <cuda_runtime.h>
#include <math.h>

// TtMambaSSM (B=256, D=5120, R=160, N=16)
//   zero  : clear TBC accumulator
//   gemm1 : TBC = x @ [W_dt_low|W_B|W_C]   (256x192xK5120, split-K=40 + atomics)
//   gemm2 : delta = softplus(T @ W_dt + b) (256x5120xK160)
//   elem  : out = x*(D + delta*BC) + sum_n exp(delta*A)*h0*Cp  (1280 blocks)

typedef unsigned long long ull;

#define Bsz 256
#define Dsz 5120
#define NC  192

__device__ float g_TBC[Bsz * NC];
__device__ float g_delta[Bsz * Dsz];

__device__ __forceinline__ ull pack2(float lo, float hi) {
    ull r; asm("mov.b64 %0, {%1, %2};" : "=l"(r) : "f"(lo), "f"(hi)); return r;
}
__device__ __forceinline__ void ffma2(ull& d, ull a, ull b) {
    asm("fma.rn.f32x2 %0, %1, %2, %0;" : "+l"(d) : "l"(a), "l"(b));
}
__device__ __forceinline__ float2 unpack2(ull v) {
    float2 f; asm("mov.b64 {%0, %1}, %2;" : "=f"(f.x), "=f"(f.y) : "l"(v)); return f;
}

__global__ void zero_kernel() {
    int q = blockIdx.x * 256 + threadIdx.x;
    if (q < Bsz * NC / 4) *(float4*)(g_TBC + q * 4) = make_float4(0.f, 0.f, 0.f, 0.f);
}

// virtual concatenated weight read: float4 at col j of [W_dt_low | W_B | W_C]
__device__ __forceinline__ float4 loadW(const float* __restrict__ Wlow,
                                        const float* __restrict__ WB,
                                        const float* __restrict__ WC,
                                        int k, int j) {
    if (j < 160) return *(const float4*)(Wlow + k * 160 + j);
    if (j < 176) return *(const float4*)(WB + k * 16 + (j - 160));
    return *(const float4*)(WC + k * 16 + (j - 176));
}

// ---------------- GEMM1: 256x192 += x @ Wcat, split-K=40, double-buffered ----------------
// grid (12, 40): 4 m-tiles(64) x 3 n-tiles(64); 256 threads; 4x4 micro (m-paired acc)
__global__ void __launch_bounds__(256) gemm1_kernel(const float* __restrict__ x,
                                                    const float* __restrict__ Wlow,
                                                    const float* __restrict__ WB,
                                                    const float* __restrict__ WC)
{
    __shared__ float As[2][16][68];
    __shared__ float Bs[2][16][64];

    const int m0 = (blockIdx.x & 3) * 64;
    const int n0 = (blockIdx.x >> 2) * 64;
    const int k0 = blockIdx.y * 128;
    const int tid = threadIdx.x;
    const int ty = tid >> 4, tx = tid & 15;
    const int lm  = tid >> 2, lkq = (tid & 3) * 4;
    const int lkk = tid >> 4, lj4 = (tid & 15) * 4;

    ull acc[2][4];
    const ull z0 = pack2(0.0f, 0.0f);
#pragma unroll
    for (int p = 0; p < 2; p++)
#pragma unroll
        for (int j = 0; j < 4; j++) acc[p][j] = z0;

    float4 av = *(const float4*)(x + (m0 + lm) * Dsz + k0 + lkq);
    float4 bv = loadW(Wlow, WB, WC, k0 + lkk, n0 + lj4);
    As[0][lkq + 0][lm] = av.x; As[0][lkq + 1][lm] = av.y;
    As[0][lkq + 2][lm] = av.z; As[0][lkq + 3][lm] = av.w;
    *(float4*)&Bs[0][lkk][lj4] = bv;
    __syncthreads();

    for (int it = 0; it < 8; it++) {
        const int cur = it & 1;
        if (it < 7) {
            const int kb = k0 + (it + 1) * 16;
            av = *(const float4*)(x + (m0 + lm) * Dsz + kb + lkq);
            bv = loadW(Wlow, WB, WC, kb + lkk, n0 + lj4);
        }
#pragma unroll
        for (int kk = 0; kk < 16; kk++) {
            longlong2 ap = *(const longlong2*)&As[cur][kk][ty * 4];
            float4 b = *(const float4*)&Bs[cur][kk][tx * 4];
            const ull aP0 = (ull)ap.x, aP1 = (ull)ap.y;
            ull bd;
            bd = pack2(b.x, b.x); ffma2(acc[0][0], aP0, bd); ffma2(acc[1][0], aP1, bd);
            bd = pack2(b.y, b.y); ffma2(acc[0][1], aP0, bd); ffma2(acc[1][1], aP1, bd);
            bd = pack2(b.z, b.z); ffma2(acc[0][2], aP0, bd); ffma2(acc[1][2], aP1, bd);
            bd = pack2(b.w, b.w); ffma2(acc[0][3], aP0, bd); ffma2(acc[1][3], aP1, bd);
        }
        if (it < 7) {
            const int nxt = cur ^ 1;
            As[nxt][lkq + 0][lm] = av.x; As[nxt][lkq + 1][lm] = av.y;
            As[nxt][lkq + 2][lm] = av.z; As[nxt][lkq + 3][lm] = av.w;
            *(float4*)&Bs[nxt][lkk][lj4] = bv;
        }
        __syncthreads();
    }
#pragma unroll
    for (int p = 0; p < 2; p++)
#pragma unroll
        for (int j = 0; j < 4; j++) {
            float2 v = unpack2(acc[p][j]);
            const int row = m0 + ty * 4 + 2 * p;
            const int col = n0 + tx * 4 + j;
            atomicAdd(&g_TBC[row * NC + col], v.x);
            atomicAdd(&g_TBC[(row + 1) * NC + col], v.y);
        }
}

// ---------------- GEMM2: delta = softplus(T @ W_dt + b), double-buffered ----------------
// grid (80, 4): n-tiles(64) x m-tiles(64); 256 threads; 4x4 micro (m-paired acc)
__global__ void __launch_bounds__(256) gemm2_kernel(const float* __restrict__ Wdt,
                                                    const float* __restrict__ bias)
{
    __shared__ float As[2][16][68];
    __shared__ float Bs[2][16][64];
    __shared__ float bias_s[64];

    const int n0 = blockIdx.x * 64;
    const int m0 = blockIdx.y * 64;
    const int tid = threadIdx.x;
    const int ty = tid >> 4, tx = tid & 15;
    const int lm  = tid >> 2, lkq = (tid & 3) * 4;
    const int lkk = tid >> 4, lj4 = (tid & 15) * 4;

    if (tid < 64) bias_s[tid] = bias[n0 + tid];

    ull acc[2][4];
    const ull z0 = pack2(0.0f, 0.0f);
#pragma unroll
    for (int p = 0; p < 2; p++)
#pragma unroll
        for (int j = 0; j < 4; j++) acc[p][j] = z0;

    float4 av = *(const float4*)(g_TBC + (m0 + lm) * NC + lkq);
    float4 bv = *(const float4*)(Wdt + lkk * Dsz + n0 + lj4);
    As[0][lkq + 0][lm] = av.x; As[0][lkq + 1][lm] = av.y;
    As[0][lkq + 2][lm] = av.z; As[0][lkq + 3][lm] = av.w;
    *(float4*)&Bs[0][lkk][lj4] = bv;
    __syncthreads();

    for (int it = 0; it < 10; it++) {
        const int cur = it & 1;
        if (it < 9) {
            const int kb = (it + 1) * 16;
            av = *(const float4*)(g_TBC + (m0 + lm) * NC + kb + lkq);
            bv = *(const float4*)(Wdt + (kb + lkk) * Dsz + n0 + lj4);
        }
#pragma unroll
        for (int kk = 0; kk < 16; kk++) {
            longlong2 ap = *(const longlong2*)&As[cur][kk][ty * 4];
            float4 b = *(const float4*)&Bs[cur][kk][tx * 4];
            const ull aP0 = (ull)ap.x, aP1 = (ull)ap.y;
            ull bd;
            bd = pack2(b.x, b.x); ffma2(acc[0][0], aP0, bd); ffma2(acc[1][0], aP1, bd);
            bd = pack2(b.y, b.y); ffma2(acc[0][1], aP0, bd); ffma2(acc[1][1], aP1, bd);
            bd = pack2(b.z, b.z); ffma2(acc[0][2], aP0, bd); ffma2(acc[1][2], aP1, bd);
            bd = pack2(b.w, b.w); ffma2(acc[0][3], aP0, bd); ffma2(acc[1][3], aP1, bd);
        }
        if (it < 9) {
            const int nxt = cur ^ 1;
            As[nxt][lkq + 0][lm] = av.x; As[nxt][lkq + 1][lm] = av.y;
            As[nxt][lkq + 2][lm] = av.z; As[nxt][lkq + 3][lm] = av.w;
            *(float4*)&Bs[nxt][lkk][lj4] = bv;
        }
        __syncthreads();
    }
#pragma unroll
    for (int p = 0; p < 2; p++)
#pragma unroll
        for (int j = 0; j < 4; j++) {
            float2 v = unpack2(acc[p][j]);
            const int row = m0 + ty * 4 + 2 * p;
            const int col = n0 + tx * 4 + j;
            const float bb = bias_s[tx * 4 + j];
            float t0 = v.x + bb, t1 = v.y + bb;
            g_delta[row * Dsz + col]       = (t0 > 20.0f) ? t0 : log1pf(expf(t0));
            g_delta[(row + 1) * Dsz + col] = (t1 > 20.0f) ? t1 : log1pf(expf(t1));
        }
}

// ---------------- elem: out = x*(D + delta*BC) + sum_n exp(delta*A)*h0*Cp ----------------
// grid (20, 64): d-chunk 256, b-chunk 4. 256 threads; lane quad per d, 4 states/lane.
__global__ void __launch_bounds__(256) elem_kernel(const float* __restrict__ x,
                                                   const float* __restrict__ Ag,
                                                   const float* __restrict__ Dg,
                                                   const float* __restrict__ h0,
                                                   float* __restrict__ out)
{
    __shared__ float delta_s[4 * 256];
    __shared__ float y_s[4 * 256];
    __shared__ float D_s[256];
    __shared__ float Cp_s[4][16];
    __shared__ float BC_s[4];

    const int d0 = blockIdx.x * 256;
    const int b0 = blockIdx.y * 4;
    const int tid = threadIdx.x;

#pragma unroll
    for (int r = 0; r < 4; r++)
        delta_s[r * 256 + tid] = g_delta[(size_t)(b0 + r) * Dsz + d0 + tid];
    D_s[tid] = Dg[d0 + tid];
    if (tid < 64) {
        const int bb = tid >> 4, n = tid & 15;
        Cp_s[bb][n] = g_TBC[(b0 + bb) * NC + 176 + n];
    }
    __syncthreads();
    if (tid < 4) {
        float s = 0.0f;
#pragma unroll
        for (int n = 0; n < 16; n++)
            s += g_TBC[(b0 + tid) * NC + 160 + n] * Cp_s[tid][n];
        BC_s[tid] = s;
    }
    __syncthreads();

    const int nq = tid & 3;       // state quad 0..3
    const int dq = tid >> 2;      // local d 0..63

#pragma unroll
    for (int i = 0; i < 4; i++) {
        const int dloc = i * 64 + dq;
        const int d = d0 + dloc;
        const float4 Av = *(const float4*)(Ag + d * 16 + nq * 4);
        float4 hv[4];
#pragma unroll
        for (int b = 0; b < 4; b++)
            hv[b] = *(const float4*)(h0 + ((size_t)(b0 + b) * Dsz + d) * 16 + nq * 4);
#pragma unroll
        for (int b = 0; b < 4; b++) {
            const float delta = delta_s[b * 256 + dloc];
            const float* Cr = &Cp_s[b][nq * 4];
            float y = __expf(delta * Av.x) * (hv[b].x * Cr[0])
                    + __expf(delta * Av.y) * (hv[b].y * Cr[1])
                    + __expf(delta * Av.z) * (hv[b].z * Cr[2])
                    + __expf(delta * Av.w) * (hv[b].w * Cr[3]);
            y += __shfl_xor_sync(0xffffffffu, y, 1);
            y += __shfl_xor_sync(0xffffffffu, y, 2);
            if (nq == 0) y_s[b * 256 + dloc] = y;
        }
    }
    __syncthreads();

#pragma unroll
    for (int r = 0; r < 4; r++) {
        const int idx = r * 256 + tid;
        const size_t g = (size_t)(b0 + r) * Dsz + d0 + tid;
        out[g] = x[g] * (D_s[tid] + delta_s[idx] * BC_s[r]) + y_s[idx];
    }
}

extern "C" void kernel_launch(void* const* d_in, const int* in_sizes, int n_in,
                              void* d_out, int out_size) {
    const float* x    = (const float*)d_in[0];
    const float* Wlow = (const float*)d_in[1];
    const float* Wdt  = (const float*)d_in[2];
    const float* bdt  = (const float*)d_in[3];
    const float* WB   = (const float*)d_in[4];
    const float* WC   = (const float*)d_in[5];
    const float* A    = (const float*)d_in[6];
    const float* D    = (const float*)d_in[7];
    const float* h0   = (const float*)d_in[8];
    float* out = (float*)d_out;

    zero_kernel<<<(Bsz * NC / 4 + 255) / 256, 256>>>();
    gemm1_kernel<<<dim3(12, 40), 256>>>(x, Wlow, WB, WC);
    gemm2_kernel<<<dim3(80, 4), 256>>>(Wdt, bdt);
    elem_kernel<<<dim3(20, 64), 256>>>(x, A, D, h0, out);
}

// round 8
// speedup vs baseline: 1.1619x; 1.0050x over previous
#include <cuda_runtime.h>
#include <math.h>

// TtMambaSSM (B=256, D=5120, R=160, N=16)
//   gemm1  : partials[ky] = x_chunk @ [W_dt_low|W_B|W_C]  (split-K=40, coalesced STG, no atomics)
//   reduce : TBC = sum_ky partials[ky]
//   gemm2  : delta = softplus(T @ W_dt + b)  (256x5120xK160)
//   elem   : out = x*(D + delta*BC) + sum_n exp(delta*A)*h0*Cp

typedef unsigned long long ull;

#define Bsz 256
#define Dsz 5120
#define NC  192
#define KSPLIT 40

__device__ float g_part[KSPLIT * Bsz * NC];
__device__ float g_TBC[Bsz * NC];
__device__ float g_delta[Bsz * Dsz];

__device__ __forceinline__ ull pack2(float lo, float hi) {
    ull r; asm("mov.b64 %0, {%1, %2};" : "=l"(r) : "f"(lo), "f"(hi)); return r;
}
__device__ __forceinline__ void ffma2(ull& d, ull a, ull b) {
    asm("fma.rn.f32x2 %0, %1, %2, %0;" : "+l"(d) : "l"(a), "l"(b));
}
__device__ __forceinline__ float2 unpack2(ull v) {
    float2 f; asm("mov.b64 {%0, %1}, %2;" : "=f"(f.x), "=f"(f.y) : "l"(v)); return f;
}

// virtual concatenated weight read: float4 at col j of [W_dt_low | W_B | W_C]
__device__ __forceinline__ float4 loadW(const float* __restrict__ Wlow,
                                        const float* __restrict__ WB,
                                        const float* __restrict__ WC,
                                        int k, int j) {
    if (j < 160) return *(const float4*)(Wlow + k * 160 + j);
    if (j < 176) return *(const float4*)(WB + k * 16 + (j - 160));
    return *(const float4*)(WC + k * 16 + (j - 176));
}

// ---------------- GEMM1: partials, no atomics ----------------
// grid (12, 40): 4 m-tiles(64) x 3 n-tiles(64); 256 threads; 4x4 micro (m-paired acc)
__global__ void __launch_bounds__(256) gemm1_kernel(const float* __restrict__ x,
                                                    const float* __restrict__ Wlow,
                                                    const float* __restrict__ WB,
                                                    const float* __restrict__ WC)
{
    __shared__ float As[2][16][68];
    __shared__ float Bs[2][16][64];

    const int m0 = (blockIdx.x & 3) * 64;
    const int n0 = (blockIdx.x >> 2) * 64;
    const int k0 = blockIdx.y * 128;
    const int tid = threadIdx.x;
    const int ty = tid >> 4, tx = tid & 15;
    const int lm  = tid >> 2, lkq = (tid & 3) * 4;
    const int lkk = tid >> 4, lj4 = (tid & 15) * 4;

    ull acc[2][4];
    const ull z0 = pack2(0.0f, 0.0f);
#pragma unroll
    for (int p = 0; p < 2; p++)
#pragma unroll
        for (int j = 0; j < 4; j++) acc[p][j] = z0;

    float4 av = *(const float4*)(x + (m0 + lm) * Dsz + k0 + lkq);
    float4 bv = loadW(Wlow, WB, WC, k0 + lkk, n0 + lj4);
    As[0][lkq + 0][lm] = av.x; As[0][lkq + 1][lm] = av.y;
    As[0][lkq + 2][lm] = av.z; As[0][lkq + 3][lm] = av.w;
    *(float4*)&Bs[0][lkk][lj4] = bv;
    __syncthreads();

    for (int it = 0; it < 8; it++) {
        const int cur = it & 1;
        if (it < 7) {
            const int kb = k0 + (it + 1) * 16;
            av = *(const float4*)(x + (m0 + lm) * Dsz + kb + lkq);
            bv = loadW(Wlow, WB, WC, kb + lkk, n0 + lj4);
        }
#pragma unroll
        for (int kk = 0; kk < 16; kk++) {
            longlong2 ap = *(const longlong2*)&As[cur][kk][ty * 4];
            float4 b = *(const float4*)&Bs[cur][kk][tx * 4];
            const ull aP0 = (ull)ap.x, aP1 = (ull)ap.y;
            ull bd;
            bd = pack2(b.x, b.x); ffma2(acc[0][0], aP0, bd); ffma2(acc[1][0], aP1, bd);
            bd = pack2(b.y, b.y); ffma2(acc[0][1], aP0, bd); ffma2(acc[1][1], aP1, bd);
            bd = pack2(b.z, b.z); ffma2(acc[0][2], aP0, bd); ffma2(acc[1][2], aP1, bd);
            bd = pack2(b.w, b.w); ffma2(acc[0][3], aP0, bd); ffma2(acc[1][3], aP1, bd);
        }
        if (it < 7) {
            const int nxt = cur ^ 1;
            As[nxt][lkq + 0][lm] = av.x; As[nxt][lkq + 1][lm] = av.y;
            As[nxt][lkq + 2][lm] = av.z; As[nxt][lkq + 3][lm] = av.w;
            *(float4*)&Bs[nxt][lkk][lj4] = bv;
        }
        __syncthreads();
    }

    // coalesced partial store: 4x STG.128, no atomics
    float* dst = g_part + (size_t)blockIdx.y * (Bsz * NC);
#pragma unroll
    for (int p = 0; p < 2; p++) {
        float2 v0 = unpack2(acc[p][0]);
        float2 v1 = unpack2(acc[p][1]);
        float2 v2 = unpack2(acc[p][2]);
        float2 v3 = unpack2(acc[p][3]);
        const int row = m0 + ty * 4 + 2 * p;
        const int col = n0 + tx * 4;
        *(float4*)(dst + row * NC + col)       = make_float4(v0.x, v1.x, v2.x, v3.x);
        *(float4*)(dst + (row + 1) * NC + col) = make_float4(v0.y, v1.y, v2.y, v3.y);
    }
}

// ---------------- reduce: TBC = sum over 40 slices ----------------
// grid 192 x 256 thr: one thread per output element, coalesced loads
__global__ void __launch_bounds__(256) reduce_kernel() {
    const int e = blockIdx.x * 256 + threadIdx.x;   // 0..49151
    float s0 = 0.f, s1 = 0.f, s2 = 0.f, s3 = 0.f;
#pragma unroll
    for (int k = 0; k < KSPLIT; k += 4) {
        s0 += g_part[(k + 0) * (Bsz * NC) + e];
        s1 += g_part[(k + 1) * (Bsz * NC) + e];
        s2 += g_part[(k + 2) * (Bsz * NC) + e];
        s3 += g_part[(k + 3) * (Bsz * NC) + e];
    }
    g_TBC[e] = (s0 + s1) + (s2 + s3);
}

// ---------------- GEMM2: delta = softplus(T @ W_dt + b), double-buffered ----------------
// grid (80, 4): n-tiles(64) x m-tiles(64); 256 threads; 4x4 micro (m-paired acc)
__global__ void __launch_bounds__(256) gemm2_kernel(const float* __restrict__ Wdt,
                                                    const float* __restrict__ bias)
{
    __shared__ float As[2][16][68];
    __shared__ float Bs[2][16][64];
    __shared__ float bias_s[64];

    const int n0 = blockIdx.x * 64;
    const int m0 = blockIdx.y * 64;
    const int tid = threadIdx.x;
    const int ty = tid >> 4, tx = tid & 15;
    const int lm  = tid >> 2, lkq = (tid & 3) * 4;
    const int lkk = tid >> 4, lj4 = (tid & 15) * 4;

    if (tid < 64) bias_s[tid] = bias[n0 + tid];

    ull acc[2][4];
    const ull z0 = pack2(0.0f, 0.0f);
#pragma unroll
    for (int p = 0; p < 2; p++)
#pragma unroll
        for (int j = 0; j < 4; j++) acc[p][j] = z0;

    float4 av = *(const float4*)(g_TBC + (m0 + lm) * NC + lkq);
    float4 bv = *(const float4*)(Wdt + lkk * Dsz + n0 + lj4);
    As[0][lkq + 0][lm] = av.x; As[0][lkq + 1][lm] = av.y;
    As[0][lkq + 2][lm] = av.z; As[0][lkq + 3][lm] = av.w;
    *(float4*)&Bs[0][lkk][lj4] = bv;
    __syncthreads();

    for (int it = 0; it < 10; it++) {
        const int cur = it & 1;
        if (it < 9) {
            const int kb = (it + 1) * 16;
            av = *(const float4*)(g_TBC + (m0 + lm) * NC + kb + lkq);
            bv = *(const float4*)(Wdt + (kb + lkk) * Dsz + n0 + lj4);
        }
#pragma unroll
        for (int kk = 0; kk < 16; kk++) {
            longlong2 ap = *(const longlong2*)&As[cur][kk][ty * 4];
            float4 b = *(const float4*)&Bs[cur][kk][tx * 4];
            const ull aP0 = (ull)ap.x, aP1 = (ull)ap.y;
            ull bd;
            bd = pack2(b.x, b.x); ffma2(acc[0][0], aP0, bd); ffma2(acc[1][0], aP1, bd);
            bd = pack2(b.y, b.y); ffma2(acc[0][1], aP0, bd); ffma2(acc[1][1], aP1, bd);
            bd = pack2(b.z, b.z); ffma2(acc[0][2], aP0, bd); ffma2(acc[1][2], aP1, bd);
            bd = pack2(b.w, b.w); ffma2(acc[0][3], aP0, bd); ffma2(acc[1][3], aP1, bd);
        }
        if (it < 9) {
            const int nxt = cur ^ 1;
            As[nxt][lkq + 0][lm] = av.x; As[nxt][lkq + 1][lm] = av.y;
            As[nxt][lkq + 2][lm] = av.z; As[nxt][lkq + 3][lm] = av.w;
            *(float4*)&Bs[nxt][lkk][lj4] = bv;
        }
        __syncthreads();
    }
#pragma unroll
    for (int p = 0; p < 2; p++)
#pragma unroll
        for (int j = 0; j < 4; j++) {
            float2 v = unpack2(acc[p][j]);
            const int row = m0 + ty * 4 + 2 * p;
            const int col = n0 + tx * 4 + j;
            const float bb = bias_s[tx * 4 + j];
            float t0 = v.x + bb, t1 = v.y + bb;
            g_delta[row * Dsz + col]       = (t0 > 20.0f) ? t0 : log1pf(expf(t0));
            g_delta[(row + 1) * Dsz + col] = (t1 > 20.0f) ? t1 : log1pf(expf(t1));
        }
}

// ---------------- elem: out = x*(D + delta*BC) + sum_n exp(delta*A)*h0*Cp ----------------
// grid (20, 64): d-chunk 256, b-chunk 4. 256 threads; lane quad per d, 4 states/lane.
__global__ void __launch_bounds__(256) elem_kernel(const float* __restrict__ x,
                                                   const float* __restrict__ Ag,
                                                   const float* __restrict__ Dg,
                                                   const float* __restrict__ h0,
                                                   float* __restrict__ out)
{
    __shared__ float delta_s[4 * 256];
    __shared__ float y_s[4 * 256];
    __shared__ float D_s[256];
    __shared__ float Cp_s[4][16];
    __shared__ float BC_s[4];

    const int d0 = blockIdx.x * 256;
    const int b0 = blockIdx.y * 4;
    const int tid = threadIdx.x;

#pragma unroll
    for (int r = 0; r < 4; r++)
        delta_s[r * 256 + tid] = g_delta[(size_t)(b0 + r) * Dsz + d0 + tid];
    D_s[tid] = Dg[d0 + tid];
    if (tid < 64) {
        const int bb = tid >> 4, n = tid & 15;
        Cp_s[bb][n] = g_TBC[(b0 + bb) * NC + 176 + n];
    }
    __syncthreads();
    if (tid < 4) {
        float s = 0.0f;
#pragma unroll
        for (int n = 0; n < 16; n++)
            s += g_TBC[(b0 + tid) * NC + 160 + n] * Cp_s[tid][n];
        BC_s[tid] = s;
    }
    __syncthreads();

    const int nq = tid & 3;       // state quad 0..3
    const int dq = tid >> 2;      // local d 0..63

#pragma unroll
    for (int i = 0; i < 4; i++) {
        const int dloc = i * 64 + dq;
        const int d = d0 + dloc;
        const float4 Av = *(const float4*)(Ag + d * 16 + nq * 4);
        float4 hv[4];
#pragma unroll
        for (int b = 0; b < 4; b++)
            hv[b] = *(const float4*)(h0 + ((size_t)(b0 + b) * Dsz + d) * 16 + nq * 4);
#pragma unroll
        for (int b = 0; b < 4; b++) {
            const float delta = delta_s[b * 256 + dloc];
            const float* Cr = &Cp_s[b][nq * 4];
            float y = __expf(delta * Av.x) * (hv[b].x * Cr[0])
                    + __expf(delta * Av.y) * (hv[b].y * Cr[1])
                    + __expf(delta * Av.z) * (hv[b].z * Cr[2])
                    + __expf(delta * Av.w) * (hv[b].w * Cr[3]);
            y += __shfl_xor_sync(0xffffffffu, y, 1);
            y += __shfl_xor_sync(0xffffffffu, y, 2);
            if (nq == 0) y_s[b * 256 + dloc] = y;
        }
    }
    __syncthreads();

#pragma unroll
    for (int r = 0; r < 4; r++) {
        const int idx = r * 256 + tid;
        const size_t g = (size_t)(b0 + r) * Dsz + d0 + tid;
        out[g] = x[g] * (D_s[tid] + delta_s[idx] * BC_s[r]) + y_s[idx];
    }
}

extern "C" void kernel_launch(void* const* d_in, const int* in_sizes, int n_in,
                              void* d_out, int out_size) {
    const float* x    = (const float*)d_in[0];
    const float* Wlow = (const float*)d_in[1];
    const float* Wdt  = (const float*)d_in[2];
    const float* bdt  = (const float*)d_in[3];
    const float* WB   = (const float*)d_in[4];
    const float* WC   = (const float*)d_in[5];
    const float* A    = (const float*)d_in[6];
    const float* D    = (const float*)d_in[7];
    const float* h0   = (const float*)d_in[8];
    float* out = (float*)d_out;

    gemm1_kernel<<<dim3(12, 40), 256>>>(x, Wlow, WB, WC);
    reduce_kernel<<<Bsz * NC / 256, 256>>>();
    gemm2_kernel<<<dim3(80, 4), 256>>>(Wdt, bdt);
    elem_kernel<<<dim3(20, 64), 256>>>(x, A, D, h0, out);
}